// round 4
// baseline (speedup 1.0000x reference)
#include <cuda_runtime.h>
#include <math.h>

#define NGRID 128
#define NG3 (NGRID*NGRID*NGRID)
#define CCH 32
#define RAD 6          // conv kernel radius; k(7)/k(0) ~ 2e-11
#define MAXN 32768

__device__ float g_field0[NG3];   // 8 MB (scatter target / z-conv input)
__device__ float g_field1[NG3];   // 8 MB (z-conv out, slab in-place, gather src)
__device__ float g_s[MAXN];       // per-particle channel-summed feature

struct Taps { float t[RAD + 1]; };

// ---------------------------------------------------------------------------
// Fused zero + MLP. Grid = 2048 blocks x 256 threads.
// Every thread zeros one float4 of g_field0 (2048*256 = NG3/4 exactly).
// Blocks [0, ceil(n/256)) additionally run the per-particle MLP.
// ---------------------------------------------------------------------------
__global__ __launch_bounds__(256)
void k_zero_mlp(const int* __restrict__ z, const float* __restrict__ emb,
                const float* __restrict__ W0, const float* __restrict__ b0,
                const float* __restrict__ W1, const float* __restrict__ b1,
                int n) {
    int gtid = blockIdx.x * 256 + threadIdx.x;
    reinterpret_cast<float4*>(g_field0)[gtid] = make_float4(0.f, 0.f, 0.f, 0.f);

    int mlp_blocks = (n + 255) / 256;
    if ((int)blockIdx.x >= mlp_blocks) return;

    __shared__ float sEmb[128 * CCH];
    __shared__ float sW0[CCH * CCH];
    __shared__ float sW1[CCH * CCH];
    __shared__ float sb0[CCH], sb1[CCH];
    for (int i = threadIdx.x; i < 128 * CCH; i += 256) sEmb[i] = emb[i];
    for (int i = threadIdx.x; i < CCH * CCH; i += 256) { sW0[i] = W0[i]; sW1[i] = W1[i]; }
    if (threadIdx.x < CCH) { sb0[threadIdx.x] = b0[threadIdx.x]; sb1[threadIdx.x] = b1[threadIdx.x]; }
    __syncthreads();

    int i = gtid;
    if (i >= n) return;
    int zi = z[i];
    float x[CCH], y[CCH];
    #pragma unroll
    for (int c = 0; c < CCH; c++) x[c] = sEmb[zi * CCH + c];
    #pragma unroll
    for (int r = 0; r < CCH; r++) {
        float a = sb0[r];
        #pragma unroll
        for (int c = 0; c < CCH; c++) a += sW0[r * CCH + c] * x[c];
        y[r] = a / (1.f + __expf(-a));               // silu
    }
    float s = 0.f;
    #pragma unroll
    for (int r = 0; r < CCH; r++) {
        float a = sb1[r];
        #pragma unroll
        for (int c = 0; c < CCH; c++) a += sW1[r * CCH + c] * y[c];
        s += a / (1.f + __expf(-a));                 // silu, then channel-sum
    }
    g_s[i] = s;
}

// ---------------------------------------------------------------------------
// Window helper: offsets = {-1,0,1,2} per axis (P=4, arange(P) - (P//2-1))
// ---------------------------------------------------------------------------
__device__ __forceinline__ void window_cell(const float* __restrict__ pos, int i, int t,
                                            float& w, int& idx) {
    const float h = 10.0f / 128.0f;     // exact in fp32
    const float inv = 1.0f / h;
    int a = t >> 4, b = (t >> 2) & 3, c = t & 3;   // x-, y-, z-offset indices
    float px = fmodf(pos[3 * i + 0], 10.0f);
    float py = fmodf(pos[3 * i + 1], 10.0f);
    float pz = fmodf(pos[3 * i + 2], 10.0f);
    int cx = (int)floorf(px / h) + a - 1;
    int cy = (int)floorf(py / h) + b - 1;
    int cz = (int)floorf(pz / h) + c - 1;
    float dx = (px - (float)cx * h) * inv;
    float dy = (py - (float)cy * h) * inv;
    float dz = (pz - (float)cz * h) * inv;
    w = __expf(-0.5f * (dx * dx + dy * dy + dz * dz));
    idx = (((cz & 127) * 128 + (cy & 127)) * 128 + (cx & 127));
}

// 64 threads per particle, 4 particles per 256-thread block
__global__ __launch_bounds__(256)
void k_scatter(const float* __restrict__ pos, int n) {
    int lp = threadIdx.x >> 6;
    int t  = threadIdx.x & 63;
    int i = blockIdx.x * 4 + lp;
    if (i >= n) return;
    float w; int idx;
    window_cell(pos, i, t, w, idx);
    atomicAdd(&g_field0[idx], w * g_s[i]);
}

__global__ __launch_bounds__(256)
void k_gather(const float* __restrict__ pos, float* __restrict__ out, int n) {
    __shared__ float part[8];
    int lp = threadIdx.x >> 6;
    int t  = threadIdx.x & 63;
    int i = blockIdx.x * 4 + lp;
    float v = 0.f;
    if (i < n) {
        float w; int idx;
        window_cell(pos, i, t, w, idx);
        v = w * g_field1[idx];
    }
    #pragma unroll
    for (int o = 16; o; o >>= 1) v += __shfl_xor_sync(0xffffffffu, v, o);
    if ((threadIdx.x & 31) == 0) part[threadIdx.x >> 5] = v;
    __syncthreads();
    if (t == 0 && i < n) out[i] = part[2 * lp] + part[2 * lp + 1];
}

// ---------------------------------------------------------------------------
// z-axis circular conv: g_field0 -> g_field1.
// Block = 1024 threads covering a 32-wide x-chunk x full 128 z (4 z per thread).
// Grid = (4 x-chunks, 128 y).
// ---------------------------------------------------------------------------
__global__ __launch_bounds__(1024)
void k_convz(Taps tp) {
    __shared__ float tile[NGRID][32];
    int tx = threadIdx.x & 31;
    int tz = threadIdx.x >> 5;            // 0..31
    int x0 = blockIdx.x * 32;
    int yy = blockIdx.y;
    const float* base = g_field0 + yy * NGRID + x0 + tx;
    #pragma unroll
    for (int zz = tz; zz < NGRID; zz += 32)
        tile[zz][tx] = base[zz * NGRID * NGRID];
    __syncthreads();
    float* ob = g_field1 + yy * NGRID + x0 + tx;
    #pragma unroll
    for (int zz = tz; zz < NGRID; zz += 32) {
        float acc = tp.t[0] * tile[zz][tx];
        #pragma unroll
        for (int d = 1; d <= RAD; d++)
            acc += tp.t[d] * (tile[(zz + d) & 127][tx] + tile[(zz - d) & 127][tx]);
        ob[zz * NGRID * NGRID] = acc;
    }
}

// ---------------------------------------------------------------------------
// Fused y-then-x conv on one z-slice, IN PLACE on g_field1.
// Grid = 128 blocks (one per z), 1024 threads, 64 KB dynamic smem.
// Processed in two 8-element half-passes to keep regs under 64/thread.
// ---------------------------------------------------------------------------
__global__ __launch_bounds__(1024)
void k_slab(Taps tp) {
    extern __shared__ float a[];          // 128*128 floats = 64 KB
    int tid = threadIdx.x;
    float* slice = g_field1 + blockIdx.x * (NGRID * NGRID);
    float4* a4 = reinterpret_cast<float4*>(a);
    const float4* s4 = reinterpret_cast<const float4*>(slice);
    #pragma unroll
    for (int k = 0; k < 4; k++) a4[tid + k * 1024] = s4[tid + k * 1024];
    __syncthreads();

    float r[8];
    // y-conv (two half-passes of 8 registers each)
    #pragma unroll
    for (int half = 0; half < 2; half++) {
        #pragma unroll
        for (int k = 0; k < 8; k++) {
            int idx = tid + (half * 8 + k) * 1024;
            int y = idx >> 7, x = idx & 127;
            float acc = tp.t[0] * a[idx];
            #pragma unroll
            for (int d = 1; d <= RAD; d++)
                acc += tp.t[d] * (a[(((y + d) & 127) << 7) + x] + a[(((y - d) & 127) << 7) + x]);
            r[k] = acc;
        }
        __syncthreads();                 // all reads of this half done before writes
        #pragma unroll
        for (int k = 0; k < 8; k++) {
            // stash results in the OTHER buffer region is unsafe in-place; instead
            // write to a temp row region: we write after full barrier, but the second
            // half still needs original values -> so buffer half-results in slice (gmem)
            slice[tid + (half * 8 + k) * 1024] = r[k];
        }
        __syncthreads();
    }
    // reload y-conv result from gmem (L2-hot) into smem
    #pragma unroll
    for (int k = 0; k < 4; k++) a4[tid + k * 1024] = s4[tid + k * 1024];
    __syncthreads();
    // x-conv, write final to gmem
    #pragma unroll
    for (int half = 0; half < 2; half++) {
        #pragma unroll
        for (int k = 0; k < 8; k++) {
            int idx = tid + (half * 8 + k) * 1024;
            int ybase = idx & ~127, x = idx & 127;
            float acc = tp.t[0] * a[idx];
            #pragma unroll
            for (int d = 1; d <= RAD; d++)
                acc += tp.t[d] * (a[ybase + ((x + d) & 127)] + a[ybase + ((x - d) & 127)]);
            r[k] = acc;
        }
        #pragma unroll
        for (int k = 0; k < 8; k++)
            slice[tid + (half * 8 + k) * 1024] = r[k];
    }
}

// ---------------------------------------------------------------------------
// Host-side exact taps: inverse DFT of exp(-0.5*sig^2*k^2) with sig = h = L/NG.
// ---------------------------------------------------------------------------
static Taps make_taps() {
    Taps tp;
    for (int d = 0; d <= RAD; d++) {
        double acc = 1.0;  // m = 0
        for (int m = 1; m < 64; m++) {
            double a = M_PI * (double)m / 64.0;
            acc += 2.0 * exp(-0.5 * a * a) * cos(M_PI * (double)(m * d) / 64.0);
        }
        acc += exp(-0.5 * M_PI * M_PI) * cos(M_PI * (double)d);  // m = 64 (Nyquist)
        tp.t[d] = (float)(acc / 128.0);
    }
    return tp;
}

extern "C" void kernel_launch(void* const* d_in, const int* in_sizes, int n_in,
                              void* d_out, int out_size) {
    const int*   z   = (const int*)  d_in[0];
    const float* pos = (const float*)d_in[1];
    // d_in[2] = batch (all zeros, NBATCH=1) — unused
    const float* emb = (const float*)d_in[3];
    const float* W0  = (const float*)d_in[4];
    const float* b0  = (const float*)d_in[5];
    const float* W1  = (const float*)d_in[6];
    const float* b1  = (const float*)d_in[7];
    float* out = (float*)d_out;
    int n = in_sizes[0];

    Taps tp = make_taps();   // host double math; baked into the captured graph

    static bool attr_done = false;
    if (!attr_done) {
        cudaFuncSetAttribute(k_slab, cudaFuncAttributeMaxDynamicSharedMemorySize, 65536);
        attr_done = true;
    }

    k_zero_mlp<<<2048, 256>>>(z, emb, W0, b0, W1, b1, n);
    k_scatter<<<(n + 3) / 4, 256>>>(pos, n);
    k_convz<<<dim3(4, 128), 1024>>>(tp);        // z-axis: f0 -> f1
    k_slab<<<128, 1024, 65536>>>(tp);           // y+x axes, in place on f1
    k_gather<<<(n + 3) / 4, 256>>>(pos, out, n);
}

// round 5
// speedup vs baseline: 1.1008x; 1.1008x over previous
#include <cuda_runtime.h>
#include <math.h>

#define NGRID 128
#define NG3 (NGRID*NGRID*NGRID)
#define CCH 32
#define RAD 5          // conv kernel radius; neglected mass ~3e-8 relative
#define MAXN 32768

__device__ float g_field0[NG3];   // 8 MB (scatter target / z-conv input)
__device__ float g_field1[NG3];   // 8 MB (z-conv out, slab in-place, gather src)
__device__ float g_s[MAXN];       // per-particle channel-summed feature

struct Taps { float t[RAD + 1]; };

// ---------------------------------------------------------------------------
// Fused zero + MLP. Grid = 2048 blocks x 256 threads.
// Every thread zeros one float4 of g_field0 (2048*256 = NG3/4 exactly).
// Blocks [0, ceil(n/256)) additionally run the per-particle MLP.
// ---------------------------------------------------------------------------
__global__ __launch_bounds__(256)
void k_zero_mlp(const int* __restrict__ z, const float* __restrict__ emb,
                const float* __restrict__ W0, const float* __restrict__ b0,
                const float* __restrict__ W1, const float* __restrict__ b1,
                int n) {
    int gtid = blockIdx.x * 256 + threadIdx.x;
    reinterpret_cast<float4*>(g_field0)[gtid] = make_float4(0.f, 0.f, 0.f, 0.f);

    int mlp_blocks = (n + 255) / 256;
    if ((int)blockIdx.x >= mlp_blocks) return;

    __shared__ float sEmb[128 * CCH];
    __shared__ float sW0[CCH * CCH];
    __shared__ float sW1[CCH * CCH];
    __shared__ float sb0[CCH], sb1[CCH];
    for (int i = threadIdx.x; i < 128 * CCH; i += 256) sEmb[i] = emb[i];
    for (int i = threadIdx.x; i < CCH * CCH; i += 256) { sW0[i] = W0[i]; sW1[i] = W1[i]; }
    if (threadIdx.x < CCH) { sb0[threadIdx.x] = b0[threadIdx.x]; sb1[threadIdx.x] = b1[threadIdx.x]; }
    __syncthreads();

    int i = gtid;
    if (i >= n) return;
    int zi = z[i];
    float x[CCH], y[CCH];
    #pragma unroll
    for (int c = 0; c < CCH; c++) x[c] = sEmb[zi * CCH + c];
    #pragma unroll
    for (int r = 0; r < CCH; r++) {
        float a = sb0[r];
        #pragma unroll
        for (int c = 0; c < CCH; c++) a += sW0[r * CCH + c] * x[c];
        y[r] = a / (1.f + __expf(-a));               // silu
    }
    float s = 0.f;
    #pragma unroll
    for (int r = 0; r < CCH; r++) {
        float a = sb1[r];
        #pragma unroll
        for (int c = 0; c < CCH; c++) a += sW1[r * CCH + c] * y[c];
        s += a / (1.f + __expf(-a));                 // silu, then channel-sum
    }
    g_s[i] = s;
}

// ---------------------------------------------------------------------------
// Window helper: offsets = {-1,0,1,2} per axis (P=4, arange(P) - (P//2-1))
// ---------------------------------------------------------------------------
__device__ __forceinline__ void window_cell(const float* __restrict__ pos, int i, int t,
                                            float& w, int& idx) {
    const float h = 10.0f / 128.0f;     // exact in fp32
    const float inv = 1.0f / h;
    int a = t >> 4, b = (t >> 2) & 3, c = t & 3;   // x-, y-, z-offset indices
    float px = fmodf(pos[3 * i + 0], 10.0f);
    float py = fmodf(pos[3 * i + 1], 10.0f);
    float pz = fmodf(pos[3 * i + 2], 10.0f);
    int cx = (int)floorf(px / h) + a - 1;
    int cy = (int)floorf(py / h) + b - 1;
    int cz = (int)floorf(pz / h) + c - 1;
    float dx = (px - (float)cx * h) * inv;
    float dy = (py - (float)cy * h) * inv;
    float dz = (pz - (float)cz * h) * inv;
    w = __expf(-0.5f * (dx * dx + dy * dy + dz * dz));
    idx = (((cz & 127) * 128 + (cy & 127)) * 128 + (cx & 127));
}

// 64 threads per particle, 4 particles per 256-thread block
__global__ __launch_bounds__(256)
void k_scatter(const float* __restrict__ pos, int n) {
    int lp = threadIdx.x >> 6;
    int t  = threadIdx.x & 63;
    int i = blockIdx.x * 4 + lp;
    if (i >= n) return;
    float w; int idx;
    window_cell(pos, i, t, w, idx);
    atomicAdd(&g_field0[idx], w * g_s[i]);
}

__global__ __launch_bounds__(256)
void k_gather(const float* __restrict__ pos, float* __restrict__ out, int n) {
    __shared__ float part[8];
    int lp = threadIdx.x >> 6;
    int t  = threadIdx.x & 63;
    int i = blockIdx.x * 4 + lp;
    float v = 0.f;
    if (i < n) {
        float w; int idx;
        window_cell(pos, i, t, w, idx);
        v = w * g_field1[idx];
    }
    #pragma unroll
    for (int o = 16; o; o >>= 1) v += __shfl_xor_sync(0xffffffffu, v, o);
    if ((threadIdx.x & 31) == 0) part[threadIdx.x >> 5] = v;
    __syncthreads();
    if (t == 0 && i < n) out[i] = part[2 * lp] + part[2 * lp + 1];
}

// ---------------------------------------------------------------------------
// z-axis circular conv: g_field0 -> g_field1, halo-tiled.
// Block = 256 threads: 32-wide x-chunk x 64-z output chunk (8 z per thread).
// Tile holds 64 + 2*RAD z-rows; inner loop has NO modulo ops.
// Grid = (4 x-chunks, 2 z-chunks, 128 y) = 1024 blocks.
// ---------------------------------------------------------------------------
__global__ __launch_bounds__(256)
void k_convz(Taps tp) {
    __shared__ float tile[64 + 2 * RAD][32];
    int tx = threadIdx.x & 31;
    int tz = threadIdx.x >> 5;            // 0..7
    int x0 = blockIdx.x * 32;
    int z0 = blockIdx.y * 64;
    int yy = blockIdx.z;
    const float* base = g_field0 + yy * NGRID + x0 + tx;
    #pragma unroll
    for (int r = tz; r < 64 + 2 * RAD; r += 8) {
        int gz = (z0 + r - RAD) & 127;
        tile[r][tx] = base[gz * NGRID * NGRID];
    }
    __syncthreads();
    float* ob = g_field1 + yy * NGRID + x0 + tx;
    #pragma unroll
    for (int r = tz; r < 64; r += 8) {
        int lz = r + RAD;
        float acc = tp.t[0] * tile[lz][tx];
        #pragma unroll
        for (int d = 1; d <= RAD; d++)
            acc += tp.t[d] * (tile[lz + d][tx] + tile[lz - d][tx]);
        ob[(z0 + r) * NGRID * NGRID] = acc;
    }
}

// ---------------------------------------------------------------------------
// Fused y-then-x conv on one z-slice, double smem buffer, in place on g_field1.
// Grid = 128 blocks (one per z), 1024 threads, 128 KB dynamic smem.
// a = input slice, b = y-conv result; single barrier between passes.
// ---------------------------------------------------------------------------
__global__ __launch_bounds__(1024)
void k_slab(Taps tp) {
    extern __shared__ float sm[];         // 2 * 128*128 floats = 128 KB
    float* a = sm;
    float* b = sm + NGRID * NGRID;
    int tid = threadIdx.x;
    float* slice = g_field1 + blockIdx.x * (NGRID * NGRID);
    float4* a4 = reinterpret_cast<float4*>(a);
    const float4* s4 = reinterpret_cast<const float4*>(slice);
    #pragma unroll
    for (int k = 0; k < 4; k++) a4[tid + k * 1024] = s4[tid + k * 1024];
    __syncthreads();

    // y-conv: a -> b
    #pragma unroll
    for (int k = 0; k < 16; k++) {
        int idx = tid + k * 1024;
        int y = idx >> 7, x = idx & 127;
        float acc = tp.t[0] * a[idx];
        #pragma unroll
        for (int d = 1; d <= RAD; d++)
            acc += tp.t[d] * (a[(((y + d) & 127) << 7) + x] + a[(((y - d) & 127) << 7) + x]);
        b[idx] = acc;
    }
    __syncthreads();

    // x-conv: b -> gmem
    #pragma unroll
    for (int k = 0; k < 16; k++) {
        int idx = tid + k * 1024;
        int ybase = idx & ~127, x = idx & 127;
        float acc = tp.t[0] * b[idx];
        #pragma unroll
        for (int d = 1; d <= RAD; d++)
            acc += tp.t[d] * (b[ybase + ((x + d) & 127)] + b[ybase + ((x - d) & 127)]);
        slice[idx] = acc;
    }
}

// ---------------------------------------------------------------------------
// Host-side exact taps: inverse DFT of exp(-0.5*sig^2*k^2) with sig = h = L/NG.
// ---------------------------------------------------------------------------
static Taps make_taps() {
    Taps tp;
    for (int d = 0; d <= RAD; d++) {
        double acc = 1.0;  // m = 0
        for (int m = 1; m < 64; m++) {
            double a = M_PI * (double)m / 64.0;
            acc += 2.0 * exp(-0.5 * a * a) * cos(M_PI * (double)(m * d) / 64.0);
        }
        acc += exp(-0.5 * M_PI * M_PI) * cos(M_PI * (double)d);  // m = 64 (Nyquist)
        tp.t[d] = (float)(acc / 128.0);
    }
    return tp;
}

extern "C" void kernel_launch(void* const* d_in, const int* in_sizes, int n_in,
                              void* d_out, int out_size) {
    const int*   z   = (const int*)  d_in[0];
    const float* pos = (const float*)d_in[1];
    // d_in[2] = batch (all zeros, NBATCH=1) — unused
    const float* emb = (const float*)d_in[3];
    const float* W0  = (const float*)d_in[4];
    const float* b0  = (const float*)d_in[5];
    const float* W1  = (const float*)d_in[6];
    const float* b1  = (const float*)d_in[7];
    float* out = (float*)d_out;
    int n = in_sizes[0];

    Taps tp = make_taps();   // host double math; baked into the captured graph

    static bool attr_done = false;
    if (!attr_done) {
        cudaFuncSetAttribute(k_slab, cudaFuncAttributeMaxDynamicSharedMemorySize, 131072);
        attr_done = true;
    }

    k_zero_mlp<<<2048, 256>>>(z, emb, W0, b0, W1, b1, n);
    k_scatter<<<(n + 3) / 4, 256>>>(pos, n);
    k_convz<<<dim3(4, 2, 128), 256>>>(tp);      // z-axis: f0 -> f1 (haloed tiles)
    k_slab<<<128, 1024, 131072>>>(tp);          // y+x axes, in place on f1
    k_gather<<<(n + 3) / 4, 256>>>(pos, out, n);
}

// round 6
// speedup vs baseline: 1.2153x; 1.1040x over previous
#include <cuda_runtime.h>
#include <math.h>

#define NGRID 128
#define NG3 (NGRID*NGRID*NGRID)
#define CCH 32
#define RAD 5          // conv kernel radius; neglected mass ~3e-8 relative
#define MAXN 32768
#define SP 129         // padded smem row stride (odd => conflict-free transposed access)

__device__ float g_field0[NG3];   // 8 MB (scatter target / z-conv input)
__device__ float g_field1[NG3];   // 8 MB (z-conv out, slab in-place, gather src)
__device__ float g_s[MAXN];       // per-particle channel-summed feature

struct Taps { float t[RAD + 1]; };

// ---------------------------------------------------------------------------
// Fused zero + MLP. Grid = 2048 blocks x 256 threads.
// ---------------------------------------------------------------------------
__global__ __launch_bounds__(256)
void k_zero_mlp(const int* __restrict__ z, const float* __restrict__ emb,
                const float* __restrict__ W0, const float* __restrict__ b0,
                const float* __restrict__ W1, const float* __restrict__ b1,
                int n) {
    int gtid = blockIdx.x * 256 + threadIdx.x;
    reinterpret_cast<float4*>(g_field0)[gtid] = make_float4(0.f, 0.f, 0.f, 0.f);

    int mlp_blocks = (n + 255) / 256;
    if ((int)blockIdx.x >= mlp_blocks) return;

    __shared__ float sEmb[128 * CCH];
    __shared__ float sW0[CCH * CCH];
    __shared__ float sW1[CCH * CCH];
    __shared__ float sb0[CCH], sb1[CCH];
    for (int i = threadIdx.x; i < 128 * CCH; i += 256) sEmb[i] = emb[i];
    for (int i = threadIdx.x; i < CCH * CCH; i += 256) { sW0[i] = W0[i]; sW1[i] = W1[i]; }
    if (threadIdx.x < CCH) { sb0[threadIdx.x] = b0[threadIdx.x]; sb1[threadIdx.x] = b1[threadIdx.x]; }
    __syncthreads();

    int i = gtid;
    if (i >= n) return;
    int zi = z[i];
    float x[CCH], y[CCH];
    #pragma unroll
    for (int c = 0; c < CCH; c++) x[c] = sEmb[zi * CCH + c];
    #pragma unroll
    for (int r = 0; r < CCH; r++) {
        float a = sb0[r];
        #pragma unroll
        for (int c = 0; c < CCH; c++) a += sW0[r * CCH + c] * x[c];
        y[r] = a / (1.f + __expf(-a));               // silu
    }
    float s = 0.f;
    #pragma unroll
    for (int r = 0; r < CCH; r++) {
        float a = sb1[r];
        #pragma unroll
        for (int c = 0; c < CCH; c++) a += sW1[r * CCH + c] * y[c];
        s += a / (1.f + __expf(-a));                 // silu, then channel-sum
    }
    g_s[i] = s;
}

// ---------------------------------------------------------------------------
// Window helper: offsets = {-1,0,1,2} per axis (P=4, arange(P) - (P//2-1))
// ---------------------------------------------------------------------------
__device__ __forceinline__ void window_cell(const float* __restrict__ pos, int i, int t,
                                            float& w, int& idx) {
    const float h = 10.0f / 128.0f;     // exact in fp32
    const float inv = 1.0f / h;
    int a = t >> 4, b = (t >> 2) & 3, c = t & 3;   // x-, y-, z-offset indices
    float px = fmodf(pos[3 * i + 0], 10.0f);
    float py = fmodf(pos[3 * i + 1], 10.0f);
    float pz = fmodf(pos[3 * i + 2], 10.0f);
    int cx = (int)floorf(px / h) + a - 1;
    int cy = (int)floorf(py / h) + b - 1;
    int cz = (int)floorf(pz / h) + c - 1;
    float dx = (px - (float)cx * h) * inv;
    float dy = (py - (float)cy * h) * inv;
    float dz = (pz - (float)cz * h) * inv;
    w = __expf(-0.5f * (dx * dx + dy * dy + dz * dz));
    idx = (((cz & 127) * 128 + (cy & 127)) * 128 + (cx & 127));
}

// 64 threads per particle, 4 particles per 256-thread block
__global__ __launch_bounds__(256)
void k_scatter(const float* __restrict__ pos, int n) {
    int lp = threadIdx.x >> 6;
    int t  = threadIdx.x & 63;
    int i = blockIdx.x * 4 + lp;
    if (i >= n) return;
    float w; int idx;
    window_cell(pos, i, t, w, idx);
    atomicAdd(&g_field0[idx], w * g_s[i]);
}

__global__ __launch_bounds__(256)
void k_gather(const float* __restrict__ pos, float* __restrict__ out, int n) {
    __shared__ float part[8];
    int lp = threadIdx.x >> 6;
    int t  = threadIdx.x & 63;
    int i = blockIdx.x * 4 + lp;
    float v = 0.f;
    if (i < n) {
        float w; int idx;
        window_cell(pos, i, t, w, idx);
        v = w * g_field1[idx];
    }
    #pragma unroll
    for (int o = 16; o; o >>= 1) v += __shfl_xor_sync(0xffffffffu, v, o);
    if ((threadIdx.x & 31) == 0) part[threadIdx.x >> 5] = v;
    __syncthreads();
    if (t == 0 && i < n) out[i] = part[2 * lp] + part[2 * lp + 1];
}

// ---------------------------------------------------------------------------
// z-axis circular conv: g_field0 -> g_field1, halo tile + register sliding.
// Block = 256 threads: 32-wide x-chunk x 64-z output chunk (8 consecutive z
// per thread via a 18-register sliding window). Grid = (4, 2, 128).
// ---------------------------------------------------------------------------
__global__ __launch_bounds__(256)
void k_convz(Taps tp) {
    __shared__ float tile[64 + 2 * RAD][32];
    int tx = threadIdx.x & 31;
    int tz = threadIdx.x >> 5;            // 0..7
    int x0 = blockIdx.x * 32;
    int z0 = blockIdx.y * 64;
    int yy = blockIdx.z;
    const float* base = g_field0 + yy * NGRID + x0 + tx;
    #pragma unroll
    for (int r = tz; r < 64 + 2 * RAD; r += 8) {
        int gz = (z0 + r - RAD) & 127;
        tile[r][tx] = base[gz * NGRID * NGRID];
    }
    __syncthreads();
    float v[8 + 2 * RAD];
    int r0 = tz * 8;
    #pragma unroll
    for (int j = 0; j < 8 + 2 * RAD; j++) v[j] = tile[r0 + j][tx];
    float* ob = g_field1 + yy * NGRID + x0 + tx;
    #pragma unroll
    for (int k = 0; k < 8; k++) {
        float acc = tp.t[0] * v[k + RAD];
        #pragma unroll
        for (int d = 1; d <= RAD; d++)
            acc += tp.t[d] * (v[k + RAD + d] + v[k + RAD - d]);
        ob[(z0 + r0 + k) * NGRID * NGRID] = acc;
    }
}

// ---------------------------------------------------------------------------
// Fused y-then-x conv on one z-slice, in place on g_field1.
// Register sliding windows (26 loads -> 16 outputs) + transposed intermediate
// with odd row stride SP=129 => every smem access is bank-conflict-free.
// Grid = 128 blocks (one per z), 1024 threads, 2*128*129*4 = 132096 B smem.
// ---------------------------------------------------------------------------
__global__ __launch_bounds__(1024)
void k_slab(Taps tp) {
    extern __shared__ float sm[];
    float* a = sm;                 // [128][SP]  (y,x) layout
    float* b = sm + NGRID * SP;    // [128][SP]  (x,y) layout (transposed)
    int tid = threadIdx.x;
    float* slice = g_field1 + blockIdx.x * (NGRID * NGRID);

    // load slice -> a (coalesced gmem reads, conflict-free smem writes)
    #pragma unroll
    for (int k = 0; k < 16; k++) {
        int idx = tid + k * 1024;
        a[(idx >> 7) * SP + (idx & 127)] = slice[idx];
    }
    __syncthreads();

    float v[16 + 2 * RAD];
    // y-conv: a(y,x) -> b(x,y)  [thread: fixed x = tid&127, y-run of 16]
    {
        int x  = tid & 127;
        int y0 = (tid >> 7) * 16;
        #pragma unroll
        for (int j = 0; j < 16 + 2 * RAD; j++)
            v[j] = a[(((y0 + j - RAD) & 127)) * SP + x];
        #pragma unroll
        for (int k = 0; k < 16; k++) {
            float acc = tp.t[0] * v[k + RAD];
            #pragma unroll
            for (int d = 1; d <= RAD; d++)
                acc += tp.t[d] * (v[k + RAD + d] + v[k + RAD - d]);
            b[x * SP + y0 + k] = acc;      // lanes: consecutive x -> stride SP (odd) -> no conflicts
        }
    }
    __syncthreads();

    // x-conv: b(x,y) -> a(y,x)  [thread: fixed y = tid&127, x-run of 16]
    {
        int y  = tid & 127;
        int x0 = (tid >> 7) * 16;
        #pragma unroll
        for (int j = 0; j < 16 + 2 * RAD; j++)
            v[j] = b[(((x0 + j - RAD) & 127)) * SP + y];
        #pragma unroll
        for (int k = 0; k < 16; k++) {
            float acc = tp.t[0] * v[k + RAD];
            #pragma unroll
            for (int d = 1; d <= RAD; d++)
                acc += tp.t[d] * (v[k + RAD + d] + v[k + RAD - d]);
            a[y * SP + x0 + k] = acc;      // lanes: consecutive y -> stride SP -> no conflicts
        }
    }
    __syncthreads();

    // a -> gmem (coalesced)
    #pragma unroll
    for (int k = 0; k < 16; k++) {
        int idx = tid + k * 1024;
        slice[idx] = a[(idx >> 7) * SP + (idx & 127)];
    }
}

// ---------------------------------------------------------------------------
// Host-side exact taps: inverse DFT of exp(-0.5*sig^2*k^2) with sig = h = L/NG.
// ---------------------------------------------------------------------------
static Taps make_taps() {
    Taps tp;
    for (int d = 0; d <= RAD; d++) {
        double acc = 1.0;  // m = 0
        for (int m = 1; m < 64; m++) {
            double a = M_PI * (double)m / 64.0;
            acc += 2.0 * exp(-0.5 * a * a) * cos(M_PI * (double)(m * d) / 64.0);
        }
        acc += exp(-0.5 * M_PI * M_PI) * cos(M_PI * (double)d);  // m = 64 (Nyquist)
        tp.t[d] = (float)(acc / 128.0);
    }
    return tp;
}

extern "C" void kernel_launch(void* const* d_in, const int* in_sizes, int n_in,
                              void* d_out, int out_size) {
    const int*   z   = (const int*)  d_in[0];
    const float* pos = (const float*)d_in[1];
    // d_in[2] = batch (all zeros, NBATCH=1) — unused
    const float* emb = (const float*)d_in[3];
    const float* W0  = (const float*)d_in[4];
    const float* b0  = (const float*)d_in[5];
    const float* W1  = (const float*)d_in[6];
    const float* b1  = (const float*)d_in[7];
    float* out = (float*)d_out;
    int n = in_sizes[0];

    Taps tp = make_taps();   // host double math; baked into the captured graph

    static bool attr_done = false;
    if (!attr_done) {
        cudaFuncSetAttribute(k_slab, cudaFuncAttributeMaxDynamicSharedMemorySize,
                             2 * NGRID * SP * (int)sizeof(float));
        attr_done = true;
    }

    k_zero_mlp<<<2048, 256>>>(z, emb, W0, b0, W1, b1, n);
    k_scatter<<<(n + 3) / 4, 256>>>(pos, n);
    k_convz<<<dim3(4, 2, 128), 256>>>(tp);      // z-axis: f0 -> f1 (haloed tiles)
    k_slab<<<128, 1024, 2 * NGRID * SP * sizeof(float)>>>(tp);  // y+x, in place on f1
    k_gather<<<(n + 3) / 4, 256>>>(pos, out, n);
}

// round 7
// speedup vs baseline: 1.2808x; 1.0539x over previous
#include <cuda_runtime.h>
#include <math.h>

#define NGRID 128
#define NG3 (NGRID*NGRID*NGRID)
#define CCH 32
#define RAD 5          // conv kernel radius; neglected mass ~3e-8 relative
#define MAXN 32768
#define SP 129         // padded smem row stride (odd => conflict-free transposed access)

__device__ float g_field0[NG3];   // 8 MB (scatter target / z-conv input)
__device__ float g_field1[NG3];   // 8 MB (z-conv out, slab in-place, gather src)
__device__ float g_s[MAXN];       // per-particle channel-summed feature

struct Taps { float t[RAD + 1]; };

// ---------------------------------------------------------------------------
// Fused zero + MLP. Grid = 2048 blocks x 256 threads.
// ---------------------------------------------------------------------------
__global__ __launch_bounds__(256)
void k_zero_mlp(const int* __restrict__ z, const float* __restrict__ emb,
                const float* __restrict__ W0, const float* __restrict__ b0,
                const float* __restrict__ W1, const float* __restrict__ b1,
                int n) {
    int gtid = blockIdx.x * 256 + threadIdx.x;
    reinterpret_cast<float4*>(g_field0)[gtid] = make_float4(0.f, 0.f, 0.f, 0.f);

    int mlp_blocks = (n + 255) / 256;
    if ((int)blockIdx.x >= mlp_blocks) return;

    __shared__ float sEmb[128 * CCH];
    __shared__ float sW0[CCH * CCH];
    __shared__ float sW1[CCH * CCH];
    __shared__ float sb0[CCH], sb1[CCH];
    for (int i = threadIdx.x; i < 128 * CCH; i += 256) sEmb[i] = emb[i];
    for (int i = threadIdx.x; i < CCH * CCH; i += 256) { sW0[i] = W0[i]; sW1[i] = W1[i]; }
    if (threadIdx.x < CCH) { sb0[threadIdx.x] = b0[threadIdx.x]; sb1[threadIdx.x] = b1[threadIdx.x]; }
    __syncthreads();

    int i = gtid;
    if (i >= n) return;
    int zi = z[i];
    float x[CCH], y[CCH];
    #pragma unroll
    for (int c = 0; c < CCH; c++) x[c] = sEmb[zi * CCH + c];
    #pragma unroll
    for (int r = 0; r < CCH; r++) {
        float a = sb0[r];
        #pragma unroll
        for (int c = 0; c < CCH; c++) a += sW0[r * CCH + c] * x[c];
        y[r] = a / (1.f + __expf(-a));               // silu
    }
    float s = 0.f;
    #pragma unroll
    for (int r = 0; r < CCH; r++) {
        float a = sb1[r];
        #pragma unroll
        for (int c = 0; c < CCH; c++) a += sW1[r * CCH + c] * y[c];
        s += a / (1.f + __expf(-a));                 // silu, then channel-sum
    }
    g_s[i] = s;
}

// ---------------------------------------------------------------------------
// Separable window, one WARP per particle.
// Lanes 0..11 compute the 12 axis-exps (axis = lane>>2, offset = lane&3),
// broadcast via shfl; each lane handles cells t = lane and lane+32.
// Cell t: a=t>>4 (x-off), b=(t>>2)&3 (y-off), c=t&3 (z-off), matching ref.
// ---------------------------------------------------------------------------
__device__ __forceinline__ void warp_window(const float* __restrict__ pos, int i, int lane,
                                            float& w0, int& idx0, float& w1, int& idx1) {
    const float h = 10.0f / 128.0f;     // exact in fp32
    const float inv = 1.0f / h;
    float px = fmodf(__ldg(&pos[3 * i + 0]), 10.0f);
    float py = fmodf(__ldg(&pos[3 * i + 1]), 10.0f);
    float pz = fmodf(__ldg(&pos[3 * i + 2]), 10.0f);
    int bx = (int)floorf(px * inv);
    int by = (int)floorf(py * inv);
    int bz = (int)floorf(pz * inv);

    // lanes 0..11: one exp each
    int ax = lane >> 2, off = lane & 3;
    float pw = (ax == 0) ? px : (ax == 1) ? py : pz;
    int   bb = (ax == 0) ? bx : (ax == 1) ? by : bz;
    int cc = bb + off - 1;
    float d = (pw - (float)cc * h) * inv;
    float e = __expf(-0.5f * d * d);

    #pragma unroll
    for (int half = 0; half < 2; half++) {
        int t = lane + half * 32;
        int a = t >> 4, b = (t >> 2) & 3, c = t & 3;
        float wx = __shfl_sync(0xffffffffu, e, a);
        float wy = __shfl_sync(0xffffffffu, e, 4 + b);
        float wz = __shfl_sync(0xffffffffu, e, 8 + c);
        int cx = (bx + a - 1) & 127;
        int cy = (by + b - 1) & 127;
        int cz = (bz + c - 1) & 127;
        float w = wx * wy * wz;
        int idx = ((cz << 7) + cy << 7) + cx;
        if (half == 0) { w0 = w; idx0 = idx; } else { w1 = w; idx1 = idx; }
    }
}

// 8 warps (particles) per 256-thread block
__global__ __launch_bounds__(256)
void k_scatter(const float* __restrict__ pos, int n) {
    int i = (blockIdx.x * 256 + threadIdx.x) >> 5;
    int lane = threadIdx.x & 31;
    if (i >= n) return;
    float w0, w1; int idx0, idx1;
    warp_window(pos, i, lane, w0, idx0, w1, idx1);
    float s = __ldg(&g_s[i]);
    atomicAdd(&g_field0[idx0], w0 * s);
    atomicAdd(&g_field0[idx1], w1 * s);
}

__global__ __launch_bounds__(256)
void k_gather(const float* __restrict__ pos, float* __restrict__ out, int n) {
    int i = (blockIdx.x * 256 + threadIdx.x) >> 5;
    int lane = threadIdx.x & 31;
    if (i >= n) return;
    float w0, w1; int idx0, idx1;
    warp_window(pos, i, lane, w0, idx0, w1, idx1);
    float v = w0 * __ldg(&g_field1[idx0]) + w1 * __ldg(&g_field1[idx1]);
    #pragma unroll
    for (int o = 16; o; o >>= 1) v += __shfl_xor_sync(0xffffffffu, v, o);
    if (lane == 0) out[i] = v;
}

// ---------------------------------------------------------------------------
// z-axis circular conv: g_field0 -> g_field1, halo tile + register sliding.
// Block = 256 threads: 32-wide x-chunk x 64-z output chunk. Grid = (4, 2, 128).
// ---------------------------------------------------------------------------
__global__ __launch_bounds__(256)
void k_convz(Taps tp) {
    __shared__ float tile[64 + 2 * RAD][32];
    int tx = threadIdx.x & 31;
    int tz = threadIdx.x >> 5;            // 0..7
    int x0 = blockIdx.x * 32;
    int z0 = blockIdx.y * 64;
    int yy = blockIdx.z;
    const float* base = g_field0 + yy * NGRID + x0 + tx;
    #pragma unroll
    for (int r = tz; r < 64 + 2 * RAD; r += 8) {
        int gz = (z0 + r - RAD) & 127;
        tile[r][tx] = base[gz * NGRID * NGRID];
    }
    __syncthreads();
    float v[8 + 2 * RAD];
    int r0 = tz * 8;
    #pragma unroll
    for (int j = 0; j < 8 + 2 * RAD; j++) v[j] = tile[r0 + j][tx];
    float* ob = g_field1 + yy * NGRID + x0 + tx;
    #pragma unroll
    for (int k = 0; k < 8; k++) {
        float acc = tp.t[0] * v[k + RAD];
        #pragma unroll
        for (int d = 1; d <= RAD; d++)
            acc += tp.t[d] * (v[k + RAD + d] + v[k + RAD - d]);
        ob[(z0 + r0 + k) * NGRID * NGRID] = acc;
    }
}

// ---------------------------------------------------------------------------
// Fused y-then-x conv on one z-slice, in place on g_field1.
// Register sliding windows + transposed intermediate (odd stride SP=129,
// all smem accesses conflict-free). x-pass writes DIRECTLY to gmem (float4).
// Grid = 128 blocks (one per z), 1024 threads, 2*128*129*4 B smem.
// ---------------------------------------------------------------------------
__global__ __launch_bounds__(1024)
void k_slab(Taps tp) {
    extern __shared__ float sm[];
    float* a = sm;                 // [128][SP]  (y,x) layout
    float* b = sm + NGRID * SP;    // [128][SP]  (x,y) layout (transposed)
    int tid = threadIdx.x;
    float* slice = g_field1 + blockIdx.x * (NGRID * NGRID);

    #pragma unroll
    for (int k = 0; k < 16; k++) {
        int idx = tid + k * 1024;
        a[(idx >> 7) * SP + (idx & 127)] = slice[idx];
    }
    __syncthreads();

    float v[16 + 2 * RAD];
    // y-conv: a(y,x) -> b(x,y)
    {
        int x  = tid & 127;
        int y0 = (tid >> 7) * 16;
        #pragma unroll
        for (int j = 0; j < 16 + 2 * RAD; j++)
            v[j] = a[(((y0 + j - RAD) & 127)) * SP + x];
        #pragma unroll
        for (int k = 0; k < 16; k++) {
            float acc = tp.t[0] * v[k + RAD];
            #pragma unroll
            for (int d = 1; d <= RAD; d++)
                acc += tp.t[d] * (v[k + RAD + d] + v[k + RAD - d]);
            b[x * SP + y0 + k] = acc;
        }
    }
    __syncthreads();

    // x-conv: b(x,y) -> gmem directly (16 consecutive floats per thread)
    {
        int y  = tid & 127;
        int x0 = (tid >> 7) * 16;
        #pragma unroll
        for (int j = 0; j < 16 + 2 * RAD; j++)
            v[j] = b[(((x0 + j - RAD) & 127)) * SP + y];
        float4* op = reinterpret_cast<float4*>(slice + y * NGRID + x0);
        #pragma unroll
        for (int q = 0; q < 4; q++) {
            float r[4];
            #pragma unroll
            for (int m = 0; m < 4; m++) {
                int k = q * 4 + m;
                float acc = tp.t[0] * v[k + RAD];
                #pragma unroll
                for (int d = 1; d <= RAD; d++)
                    acc += tp.t[d] * (v[k + RAD + d] + v[k + RAD - d]);
                r[m] = acc;
            }
            op[q] = make_float4(r[0], r[1], r[2], r[3]);
        }
    }
}

// ---------------------------------------------------------------------------
// Host-side exact taps: inverse DFT of exp(-0.5*sig^2*k^2) with sig = h = L/NG.
// ---------------------------------------------------------------------------
static Taps make_taps() {
    Taps tp;
    for (int d = 0; d <= RAD; d++) {
        double acc = 1.0;  // m = 0
        for (int m = 1; m < 64; m++) {
            double a = M_PI * (double)m / 64.0;
            acc += 2.0 * exp(-0.5 * a * a) * cos(M_PI * (double)(m * d) / 64.0);
        }
        acc += exp(-0.5 * M_PI * M_PI) * cos(M_PI * (double)d);  // m = 64 (Nyquist)
        tp.t[d] = (float)(acc / 128.0);
    }
    return tp;
}

extern "C" void kernel_launch(void* const* d_in, const int* in_sizes, int n_in,
                              void* d_out, int out_size) {
    const int*   z   = (const int*)  d_in[0];
    const float* pos = (const float*)d_in[1];
    // d_in[2] = batch (all zeros, NBATCH=1) — unused
    const float* emb = (const float*)d_in[3];
    const float* W0  = (const float*)d_in[4];
    const float* b0  = (const float*)d_in[5];
    const float* W1  = (const float*)d_in[6];
    const float* b1  = (const float*)d_in[7];
    float* out = (float*)d_out;
    int n = in_sizes[0];

    Taps tp = make_taps();   // host double math; baked into the captured graph

    static bool attr_done = false;
    if (!attr_done) {
        cudaFuncSetAttribute(k_slab, cudaFuncAttributeMaxDynamicSharedMemorySize,
                             2 * NGRID * SP * (int)sizeof(float));
        attr_done = true;
    }

    int wpb = 8;  // warps (particles) per block in scatter/gather
    k_zero_mlp<<<2048, 256>>>(z, emb, W0, b0, W1, b1, n);
    k_scatter<<<(n + wpb - 1) / wpb, 256>>>(pos, n);
    k_convz<<<dim3(4, 2, 128), 256>>>(tp);      // z-axis: f0 -> f1 (haloed tiles)
    k_slab<<<128, 1024, 2 * NGRID * SP * sizeof(float)>>>(tp);  // y+x, in place on f1
    k_gather<<<(n + wpb - 1) / wpb, 256>>>(pos, out, n);
}